// round 5
// baseline (speedup 1.0000x reference)
#include <cuda_runtime.h>
#include <math.h>

#define NROWS 8192
#define DIMK  512
#define KTOP  10
#define SCALE 0.04419417382415922f   // 512^-0.5

// Scratch embeddings (bss, no allocation)
__device__ float g_eh[NROWS * DIMK];   // pre-scaled by SCALE
__device__ float g_et[NROWS * DIMK];

// Packed fp32x2 FMA (sm_103a): c += a * b on both lanes
__device__ __forceinline__ void ffma2(float2& c, float2 a, float2 b) {
    asm("fma.rn.f32x2 %0, %1, %2, %0;"
        : "+l"(*reinterpret_cast<unsigned long long*>(&c))
        : "l"(*reinterpret_cast<unsigned long long*>(&a)),
          "l"(*reinterpret_cast<unsigned long long*>(&b)));
}

// ---------------------------------------------------------------------------
// Kernel A: E = (X @ W^T + b) * sc   (unchanged; ~10% of runtime)
// ---------------------------------------------------------------------------
__global__ void embed_kernel(const float* __restrict__ X,
                             const float* __restrict__ W0, const float* __restrict__ b0,
                             const float* __restrict__ W1, const float* __restrict__ b1)
{
    const int z = blockIdx.z;
    const float* W    = z ? W1 : W0;
    const float* bias = z ? b1 : b0;
    float* out        = z ? g_et : g_eh;
    const float sc    = z ? 1.0f : SCALE;

    __shared__ float Xs[32][64];
    __shared__ float Ws[32][64];

    const int tid = threadIdx.x;
    const int rb = blockIdx.y * 64;
    const int cb = blockIdx.x * 64;
    const int ty = tid >> 5;
    const int tx = tid & 31;

    float2 acc[4][2];
    #pragma unroll
    for (int i = 0; i < 4; i++) { acc[i][0] = make_float2(0.f, 0.f); acc[i][1] = make_float2(0.f, 0.f); }

    const int lr = tid & 63;
    const int lk = (tid >> 6) * 8;

    for (int kc = 0; kc < DIMK; kc += 32) {
        __syncthreads();
        #pragma unroll
        for (int j = 0; j < 8; j += 4) {
            float4 xv = *(const float4*)(X + (size_t)(rb + lr) * DIMK + kc + lk + j);
            Xs[lk + j + 0][lr] = xv.x; Xs[lk + j + 1][lr] = xv.y;
            Xs[lk + j + 2][lr] = xv.z; Xs[lk + j + 3][lr] = xv.w;
            float4 wv = *(const float4*)(W + (size_t)(cb + lr) * DIMK + kc + lk + j);
            Ws[lk + j + 0][lr] = wv.x; Ws[lk + j + 1][lr] = wv.y;
            Ws[lk + j + 2][lr] = wv.z; Ws[lk + j + 3][lr] = wv.w;
        }
        __syncthreads();
        #pragma unroll
        for (int k = 0; k < 32; k++) {
            float4 a0 = *(const float4*)&Xs[k][ty * 8];
            float4 a1 = *(const float4*)&Xs[k][ty * 8 + 4];
            float2 wb = *(const float2*)&Ws[k][2 * tx];
            float2 ap0 = make_float2(a0.x, a0.y);
            float2 ap1 = make_float2(a0.z, a0.w);
            float2 ap2 = make_float2(a1.x, a1.y);
            float2 ap3 = make_float2(a1.z, a1.w);
            float2 bb0 = make_float2(wb.x, wb.x);
            float2 bb1 = make_float2(wb.y, wb.y);
            ffma2(acc[0][0], ap0, bb0); ffma2(acc[1][0], ap1, bb0);
            ffma2(acc[2][0], ap2, bb0); ffma2(acc[3][0], ap3, bb0);
            ffma2(acc[0][1], ap0, bb1); ffma2(acc[1][1], ap1, bb1);
            ffma2(acc[2][1], ap2, bb1); ffma2(acc[3][1], ap3, bb1);
        }
    }

    #pragma unroll
    for (int rp = 0; rp < 4; rp++) {
        #pragma unroll
        for (int cc = 0; cc < 2; cc++) {
            int col = cb + 2 * tx + cc;
            float bv = bias[col];
            int r0 = rb + ty * 8 + 2 * rp;
            out[(size_t)r0 * DIMK + col]       = (acc[rp][cc].x + bv) * sc;
            out[(size_t)(r0 + 1) * DIMK + col] = (acc[rp][cc].y + bv) * sc;
        }
    }
}

// ---------------------------------------------------------------------------
// Kernel B: 256 threads/block, 64-row stripe per block (grid=128).
// Column tiles of 256, BK=32 double-buffered, micro-tile 8x8 per thread:
// 32 FFMA2 per 4 LDS.128 per k — smem-crossbar load per FMA cut ~40% vs R3.
// __launch_bounds__(256,1) -> 255-reg budget for deep load pipelining.
// ---------------------------------------------------------------------------
#define CTILE     256
#define BK        32
#define STAGE_STRIDE 257                      // conflict-free row scans
#define AS_FLOATS    (DIMK * 64)              // 32768
#define STAGE_FLOATS (64 * STAGE_STRIDE)      // 16448 (>= 2*BK*CTILE = 16384)
#define UNION_FLOATS (STAGE_FLOATS)
#define SMEM_B_BYTES ((AS_FLOATS + UNION_FLOATS + 64 * KTOP) * 4 + 64 * KTOP * 4)

__global__ void __launch_bounds__(256, 1)
logits_topk_kernel(float* __restrict__ src_p, float* __restrict__ dst_p,
                   float* __restrict__ w_p)
{
    extern __shared__ float sm[];
    float* As   = sm;                                  // [512][64] k-major
    float* Bs   = sm + AS_FLOATS;                      // 2 x [32][256] / stage
    float* topv = Bs + UNION_FLOATS;                   // [64][10]
    int*   topi = (int*)(topv + 64 * KTOP);            // [64][10]

    const int tid = threadIdx.x;
    const int rb  = blockIdx.x * 64;
    const int ty  = tid >> 5;        // 0..7  -> rows ty*8 .. ty*8+7
    const int tx  = tid & 31;        // cols tx*8 .. tx*8+7

    for (int i = tid; i < 64 * KTOP; i += 256) {
        topv[i] = -INFINITY; topi[i] = 0;
    }

    // load A stripe: As[k][r], 64 rows x 512 k (per thread: 128 consecutive k)
    {
        const int lr = tid & 63;
        const int kb = (tid >> 6) * 128;
        const float* srcp = g_eh + (size_t)(rb + lr) * DIMK + kb;
        #pragma unroll 4
        for (int kk = 0; kk < 128; kk += 4) {
            float4 v = *(const float4*)(srcp + kk);
            As[(kb + kk + 0) * 64 + lr] = v.x;
            As[(kb + kk + 1) * 64 + lr] = v.y;
            As[(kb + kk + 2) * 64 + lr] = v.z;
            As[(kb + kk + 3) * 64 + lr] = v.w;
        }
    }
    __syncthreads();

    for (int ct = 0; ct < NROWS / CTILE; ct++) {
        const int cbase = ct * CTILE;
        const float* bsrc = g_et + (size_t)(cbase + tid) * DIMK;  // this thread's column

        float2 acc[4][8];
        #pragma unroll
        for (int i = 0; i < 4; i++)
            #pragma unroll
            for (int j = 0; j < 8; j++) acc[i][j] = make_float2(0.f, 0.f);

        // prefetch + stage chunk 0 into buffer 0 (32 k-values of own column)
        float4 pre[8];
        #pragma unroll
        for (int j = 0; j < 8; j++) pre[j] = *(const float4*)(bsrc + 4 * j);
        #pragma unroll
        for (int j = 0; j < 8; j++) {
            int kl = 4 * j;
            Bs[(kl + 0) * CTILE + tid] = pre[j].x;
            Bs[(kl + 1) * CTILE + tid] = pre[j].y;
            Bs[(kl + 2) * CTILE + tid] = pre[j].z;
            Bs[(kl + 3) * CTILE + tid] = pre[j].w;
        }

        for (int kc = 0; kc < DIMK / BK; kc++) {       // 16 chunks
            __syncthreads();
            if (kc < DIMK / BK - 1) {
                const float* ns = bsrc + (kc + 1) * BK;
                #pragma unroll
                for (int j = 0; j < 8; j++) pre[j] = *(const float4*)(ns + 4 * j);
            }
            const float* Bcur = Bs + (kc & 1) * (BK * CTILE);
            const float* Acur = As + (kc * BK) * 64 + ty * 8;
            #pragma unroll 8
            for (int k = 0; k < BK; k++) {
                float4 a0 = *(const float4*)(Acur + k * 64);
                float4 a1 = *(const float4*)(Acur + k * 64 + 4);
                float4 b0 = *(const float4*)(Bcur + k * CTILE + tx * 8);
                float4 b1 = *(const float4*)(Bcur + k * CTILE + tx * 8 + 4);
                float2 ap0 = make_float2(a0.x, a0.y);
                float2 ap1 = make_float2(a0.z, a0.w);
                float2 ap2 = make_float2(a1.x, a1.y);
                float2 ap3 = make_float2(a1.z, a1.w);
                float bsv[8] = {b0.x, b0.y, b0.z, b0.w, b1.x, b1.y, b1.z, b1.w};
                #pragma unroll
                for (int c = 0; c < 8; c++) {
                    float2 bb = make_float2(bsv[c], bsv[c]);
                    ffma2(acc[0][c], ap0, bb);
                    ffma2(acc[1][c], ap1, bb);
                    ffma2(acc[2][c], ap2, bb);
                    ffma2(acc[3][c], ap3, bb);
                }
            }
            if (kc < DIMK / BK - 1) {
                float* Bn = Bs + ((kc + 1) & 1) * (BK * CTILE);
                #pragma unroll
                for (int j = 0; j < 8; j++) {
                    int kl = 4 * j;
                    Bn[(kl + 0) * CTILE + tid] = pre[j].x;
                    Bn[(kl + 1) * CTILE + tid] = pre[j].y;
                    Bn[(kl + 2) * CTILE + tid] = pre[j].z;
                    Bn[(kl + 3) * CTILE + tid] = pre[j].w;
                }
            }
        }
        __syncthreads();   // all B-buffer reads done before staging reuse

        // stage 64x256 logits tile (stride 257 -> conflict-free row scans)
        {
            const int r0 = ty * 8;
            #pragma unroll
            for (int rp = 0; rp < 4; rp++) {
                #pragma unroll
                for (int c = 0; c < 8; c++) {
                    Bs[(r0 + 2 * rp) * STAGE_STRIDE + tx * 8 + c]     = acc[rp][c].x;
                    Bs[(r0 + 2 * rp + 1) * STAGE_STRIDE + tx * 8 + c] = acc[rp][c].y;
                }
            }
        }
        __syncthreads();

        // one thread per row: insertion into sorted top-10 (strict > keeps
        // lower index on ties, matching lax.top_k)
        if (tid < 64) {
            const int r = tid;
            float* tv = topv + r * KTOP;
            int*   ti = topi + r * KTOP;
            const float* crow = Bs + r * STAGE_STRIDE;
            float kv = tv[KTOP - 1];
            for (int c = 0; c < CTILE; c++) {
                float v = crow[c];
                if (v > kv) {
                    int j = KTOP - 1;
                    while (j > 0 && v > tv[j - 1]) {
                        tv[j] = tv[j - 1]; ti[j] = ti[j - 1]; j--;
                    }
                    tv[j] = v; ti[j] = cbase + c;
                    kv = tv[KTOP - 1];
                }
            }
        }
        __syncthreads();
    }

    // softmax + edge emission
    if (tid < 64) {
        const int r = tid, gr = rb + tid;
        float* tv = topv + r * KTOP;
        int*   ti = topi + r * KTOP;
        float m = tv[0];
        float e[KTOP]; float s = 0.f;
        #pragma unroll
        for (int j = 0; j < KTOP; j++) { e[j] = expf(tv[j] - m); s += e[j]; }
        #pragma unroll
        for (int j = 0; j < KTOP; j++) {
            int o = gr * KTOP + j;
            if (src_p) src_p[o] = (float)gr;
            if (dst_p) dst_p[o] = (float)ti[j];
            if (w_p)   w_p[o]   = e[j] / s;
        }
    }
}

// ---------------------------------------------------------------------------
extern "C" void kernel_launch(void* const* d_in, const int* in_sizes, int n_in,
                              void* d_out, int out_size)
{
    const float* X  = (const float*)d_in[0];
    const float* Wh = (const float*)d_in[1];
    const float* bh = (const float*)d_in[2];
    const float* Wt = (const float*)d_in[3];
    const float* bt = (const float*)d_in[4];

    cudaFuncSetAttribute(logits_topk_kernel,
                         cudaFuncAttributeMaxDynamicSharedMemorySize, SMEM_B_BYTES);

    embed_kernel<<<dim3(DIMK / 64, NROWS / 64, 2), 256>>>(X, Wh, bh, Wt, bt);

    const int NK = NROWS * KTOP;   // 81920
    float* out = (float*)d_out;
    float *sp = nullptr, *dp = nullptr, *wp = nullptr;
    if (out_size >= 3 * NK)      { sp = out; dp = out + NK; wp = out + 2 * NK; }
    else if (out_size == 2 * NK) { sp = out; dp = out + NK; }
    else                         { wp = out; }

    logits_topk_kernel<<<NROWS / 64, 256, SMEM_B_BYTES>>>(sp, dp, wp);
}